// round 7
// baseline (speedup 1.0000x reference)
#include <cuda_runtime.h>
#include <math.h>
#include <stdint.h>

#define BB 64
#define TT 512
#define DD 512
#define MM (BB*TT)   // 32768

// Scratch for the precomputed projections (192 MB total)
__device__ float g_ev[MM*DD];
__device__ float g_leak[MM*DD];
__device__ float g_write[MM*DD];

// ---------------------------------------------------------------------------
// Kernel A: Y[m][n] = act( sum_k X[m][k]*W[k][n] + bias[n] )
// BM=128, BN=128, BK=16, 256 threads, 8x8 per-thread tile.
// (R3-proven version, measured at the fp32 FFMA roofline.)
// ---------------------------------------------------------------------------
template<int ACT>
__global__ __launch_bounds__(256, 2)
void proj_gemm(const float* __restrict__ X, const float* __restrict__ W,
               const float* __restrict__ bias, float* __restrict__ Y)
{
    constexpr int BM = 128, BN = 128, BK = 16;
    __shared__ float As[BM*BK];
    __shared__ float Bs[BK*BN];

    const int tid = threadIdx.x;
    const int m0 = blockIdx.x * BM;
    const int n0 = blockIdx.y * BN;
    const int tx = tid & 15;
    const int ty = tid >> 4;

    const int arow = tid >> 2;
    const int acol = (tid & 3) * 4;
    const int brow = tid >> 5;
    const int bcol = (tid & 31) * 4;

    float acc[8][8];
    #pragma unroll
    for (int i = 0; i < 8; i++)
        #pragma unroll
        for (int j = 0; j < 8; j++) acc[i][j] = 0.0f;

    for (int k0 = 0; k0 < DD; k0 += BK) {
        float4 a0 = *(const float4*)&X[(size_t)(m0 + arow     ) * DD + k0 + acol];
        float4 a1 = *(const float4*)&X[(size_t)(m0 + arow + 64) * DD + k0 + acol];
        float4 b0 = *(const float4*)&W[(size_t)(k0 + brow    ) * DD + n0 + bcol];
        float4 b1 = *(const float4*)&W[(size_t)(k0 + brow + 8) * DD + n0 + bcol];
        *(float4*)&As[(arow     ) * BK + acol] = a0;
        *(float4*)&As[(arow + 64) * BK + acol] = a1;
        *(float4*)&Bs[(brow    ) * BN + bcol] = b0;
        *(float4*)&Bs[(brow + 8) * BN + bcol] = b1;
        __syncthreads();

        #pragma unroll
        for (int kk = 0; kk < BK; kk++) {
            float a[8], b[8];
            #pragma unroll
            for (int i = 0; i < 8; i++) a[i] = As[(ty * 8 + i) * BK + kk];
            float4 bA = *(const float4*)&Bs[kk * BN + tx * 8];
            float4 bC = *(const float4*)&Bs[kk * BN + tx * 8 + 4];
            b[0]=bA.x; b[1]=bA.y; b[2]=bA.z; b[3]=bA.w;
            b[4]=bC.x; b[5]=bC.y; b[6]=bC.z; b[7]=bC.w;
            #pragma unroll
            for (int i = 0; i < 8; i++)
                #pragma unroll
                for (int j = 0; j < 8; j++)
                    acc[i][j] = fmaf(a[i], b[j], acc[i][j]);
        }
        __syncthreads();
    }

    #pragma unroll
    for (int i = 0; i < 8; i++) {
        const int m = m0 + ty * 8 + i;
        #pragma unroll
        for (int j = 0; j < 8; j++) {
            const int n = n0 + tx * 8 + j;
            float v = acc[i][j] + bias[n];
            if (ACT == 1) v = 1.0f / (1.0f + expf(-v));
            Y[(size_t)m * DD + n] = v;
        }
    }
}

// ---------------------------------------------------------------------------
// Kernel B: cluster-resident scan (16 clusters x 8 CTAs, 4 batches/cluster).
//   Wp slice in registers (64 floats/thread). Register-pressure-tamed:
//   one-batch-at-a-time matvec passes (max 4 live belief temps), no
//   per-thread address caches.
// ---------------------------------------------------------------------------
#define CLUSTER_C 8
#define NCLUST 16
#define BPC 4
#define DLOC 64
#define SCAN_THREADS 512
#define BEL_BUF_BYTES (BPC*DD*4)   // 8192: distance between the two belief buffers

__global__ __launch_bounds__(SCAN_THREADS, 1) __cluster_dims__(CLUSTER_C, 1, 1)
void scan_cluster_kernel(const float* __restrict__ Wp, const float* __restrict__ bp,
                         float* __restrict__ out)
{
    __shared__ __align__(16) float bel[2][BPC][DD];      // 16 KB double-buffered
    __shared__ __align__(16) float sp[BPC][8][DLOC];     // 8 KB k-section partials

    const int tid     = threadIdx.x;
    const int d_local = tid & 63;
    const int ksec    = tid >> 6;        // 0..7
    const int kbase   = ksec * 64;

    uint32_t rank;
    asm("mov.u32 %0, %%cluster_ctarank;" : "=r"(rank));
    const int cluster_id = blockIdx.x / CLUSTER_C;
    const int b0    = cluster_id * BPC;
    const int dglob = (int)rank * DLOC + d_local;

    // ---- Persistent Wp slice in registers ----
    float w[64];
    #pragma unroll
    for (int j = 0; j < 64; j++)
        w[j] = Wp[(size_t)(kbase + j) * DD + dglob];

    // ---- init belief buffer 0 ----
    for (int i = tid; i < BPC * DD; i += SCAN_THREADS)
        (&bel[0][0][0])[i] = 0.0f;

    // ---- reducer state: threads 0..255, one per (batch, column) ----
    const int  rb     = ksec & 3;
    const bool is_red = (tid < 256);
    float bel_prev = 0.0f;
    float bpv = 0.0f;
    size_t io_base = 0;
    uint32_t la_base = 0;
    if (is_red) {
        bpv = bp[dglob];
        io_base = ((size_t)(b0 + rb) * TT) * DD + dglob;
        la_base = (uint32_t)__cvta_generic_to_shared(&bel[0][rb][dglob]);
    }

    asm volatile("barrier.cluster.arrive.aligned;" ::: "memory");
    asm volatile("barrier.cluster.wait.aligned;"   ::: "memory");

    for (int t = 0; t < TT; t++) {
        const int cur = t & 1;

        // prefetch gate inputs (latency hidden under matvec)
        float evv = 0.f, lkv = 0.f, wrv = 0.f;
        if (is_red) {
            const size_t idx = io_base + (size_t)t * DD;
            evv = g_ev[idx];
            lkv = g_leak[idx];
            wrv = g_write[idx];
        }

        // ---- matvec partials: one batch per pass (low register pressure) ----
        #pragma unroll
        for (int bb = 0; bb < BPC; bb++) {
            const float4* blv = (const float4*)&bel[cur][bb][kbase];
            float accA = 0.f, accB = 0.f;     // two chains for dep slack
            #pragma unroll
            for (int j = 0; j < 16; j++) {
                const float4 v = blv[j];      // warp-broadcast LDS.128
                accA = fmaf(v.x, w[4*j+0], accA);
                accB = fmaf(v.y, w[4*j+1], accB);
                accA = fmaf(v.z, w[4*j+2], accA);
                accB = fmaf(v.w, w[4*j+3], accB);
            }
            sp[bb][ksec][d_local] = accA + accB;
        }
        __syncthreads();

        // ---- reduce + gates + DSMEM broadcast ----
        if (is_red) {
            float s = 0.f;
            #pragma unroll
            for (int q = 0; q < 8; q++) s += sp[rb][q][d_local];
            const float cand = tanhf(s + bpv + evv);
            const float nb   = lkv * bel_prev + wrv * cand;
            bel_prev = nb;

            // write into the *other* buffer (read at t+1)
            const uint32_t la = la_base + (cur ? 0u : (uint32_t)BEL_BUF_BYTES);
            #pragma unroll
            for (int p = 0; p < CLUSTER_C; p++) {
                uint32_t ra;
                asm("mapa.shared::cluster.u32 %0, %1, %2;"
                    : "=r"(ra) : "r"(la), "r"(p));
                asm volatile("st.shared::cluster.f32 [%0], %1;"
                             :: "r"(ra), "f"(nb) : "memory");
            }
            out[io_base + (size_t)t * DD] = nb;
        }

        // one cluster barrier per step: orders DSMEM writes(t) before
        // reads(t+1) AND protects sp against overwrite at t+1.
        asm volatile("barrier.cluster.arrive.aligned;" ::: "memory");
        asm volatile("barrier.cluster.wait.aligned;"   ::: "memory");
    }
}

// ---------------------------------------------------------------------------
// Launch
// ---------------------------------------------------------------------------
extern "C" void kernel_launch(void* const* d_in, const int* in_sizes, int n_in,
                              void* d_out, int out_size)
{
    const float* evseq = (const float*)d_in[0];
    const float* We    = (const float*)d_in[1];
    const float* be    = (const float*)d_in[2];
    const float* Wp    = (const float*)d_in[3];
    const float* bp    = (const float*)d_in[4];
    const float* Wl    = (const float*)d_in[5];
    const float* bl    = (const float*)d_in[6];
    const float* Ww    = (const float*)d_in[7];
    const float* bw    = (const float*)d_in[8];
    float* out = (float*)d_out;

    float *p_ev, *p_leak, *p_write;
    cudaGetSymbolAddress((void**)&p_ev,    g_ev);
    cudaGetSymbolAddress((void**)&p_leak,  g_leak);
    cudaGetSymbolAddress((void**)&p_write, g_write);

    dim3 grid(MM / 128, DD / 128);
    dim3 blk(256);
    proj_gemm<0><<<grid, blk>>>(evseq, We, be, p_ev);
    proj_gemm<1><<<grid, blk>>>(evseq, Wl, bl, p_leak);
    proj_gemm<1><<<grid, blk>>>(evseq, Ww, bw, p_write);

    scan_cluster_kernel<<<NCLUST * CLUSTER_C, SCAN_THREADS>>>(Wp, bp, out);
}

// round 8
// speedup vs baseline: 1.5711x; 1.5711x over previous
#include <cuda_runtime.h>
#include <math.h>
#include <stdint.h>

#define BB 64
#define TT 512
#define DD 512
#define MM (BB*TT)   // 32768

typedef unsigned long long u64;

// Scratch for the precomputed projections (192 MB total)
__device__ float g_ev[MM*DD];
__device__ float g_leak[MM*DD];
__device__ float g_write[MM*DD];

// ---- packed fp32x2 helpers (Blackwell f32x2 pipe; exact IEEE fp32) ----
__device__ __forceinline__ u64 pack2(float lo, float hi) {
    u64 r; asm("mov.b64 %0, {%1, %2};" : "=l"(r) : "f"(lo), "f"(hi)); return r;
}
__device__ __forceinline__ void unpack2(u64 v, float& lo, float& hi) {
    asm("mov.b64 {%0, %1}, %2;" : "=f"(lo), "=f"(hi) : "l"(v));
}
__device__ __forceinline__ u64 ffma2(u64 a, u64 b, u64 c) {
    u64 d; asm("fma.rn.f32x2 %0, %1, %2, %3;" : "=l"(d) : "l"(a), "l"(b), "l"(c));
    return d;
}

// ---------------------------------------------------------------------------
// Kernel A: Y[m][n] = act( sum_k X[m][k]*W[k][n] + bias[n] )
// BM=128, BN=128, BK=16, 256 threads, 8x8 per-thread tile, f32x2 inner loop.
// ---------------------------------------------------------------------------
template<int ACT>
__global__ __launch_bounds__(256, 2)
void proj_gemm(const float* __restrict__ X, const float* __restrict__ W,
               const float* __restrict__ bias, float* __restrict__ Y)
{
    constexpr int BM = 128, BN = 128, BK = 16;
    __shared__ __align__(16) float As[BM*BK];
    __shared__ __align__(16) float Bs[BK*BN];

    const int tid = threadIdx.x;
    const int m0 = blockIdx.x * BM;
    const int n0 = blockIdx.y * BN;
    const int tx = tid & 15;
    const int ty = tid >> 4;

    const int arow = tid >> 2;
    const int acol = (tid & 3) * 4;
    const int brow = tid >> 5;
    const int bcol = (tid & 31) * 4;

    u64 acc2[8][4];   // [row][col-pair]
    #pragma unroll
    for (int i = 0; i < 8; i++)
        #pragma unroll
        for (int j = 0; j < 4; j++) acc2[i][j] = 0ULL;

    for (int k0 = 0; k0 < DD; k0 += BK) {
        float4 a0 = *(const float4*)&X[(size_t)(m0 + arow     ) * DD + k0 + acol];
        float4 a1 = *(const float4*)&X[(size_t)(m0 + arow + 64) * DD + k0 + acol];
        float4 b0 = *(const float4*)&W[(size_t)(k0 + brow    ) * DD + n0 + bcol];
        float4 b1 = *(const float4*)&W[(size_t)(k0 + brow + 8) * DD + n0 + bcol];
        *(float4*)&As[(arow     ) * BK + acol] = a0;
        *(float4*)&As[(arow + 64) * BK + acol] = a1;
        *(float4*)&Bs[(brow    ) * BN + bcol] = b0;
        *(float4*)&Bs[(brow + 8) * BN + bcol] = b1;
        __syncthreads();

        #pragma unroll
        for (int kk = 0; kk < BK; kk++) {
            ulonglong2 bp0 = *(const ulonglong2*)&Bs[kk * BN + tx * 8];
            ulonglong2 bp1 = *(const ulonglong2*)&Bs[kk * BN + tx * 8 + 4];
            u64 b2[4] = { bp0.x, bp0.y, bp1.x, bp1.y };
            #pragma unroll
            for (int i = 0; i < 8; i++) {
                const float av = As[(ty * 8 + i) * BK + kk];
                const u64 ap = pack2(av, av);   // alu-pipe mov.b64
                #pragma unroll
                for (int j = 0; j < 4; j++)
                    acc2[i][j] = ffma2(ap, b2[j], acc2[i][j]);
            }
        }
        __syncthreads();
    }

    #pragma unroll
    for (int i = 0; i < 8; i++) {
        const int m = m0 + ty * 8 + i;
        #pragma unroll
        for (int j = 0; j < 4; j++) {
            float lo, hi;
            unpack2(acc2[i][j], lo, hi);
            const int n = n0 + tx * 8 + 2 * j;
            float v0 = lo + bias[n];
            float v1 = hi + bias[n + 1];
            if (ACT == 1) {
                v0 = 1.0f / (1.0f + expf(-v0));
                v1 = 1.0f / (1.0f + expf(-v1));
            }
            Y[(size_t)m * DD + n]     = v0;
            Y[(size_t)m * DD + n + 1] = v1;
        }
    }
}

// ---------------------------------------------------------------------------
// Kernel B: cluster-resident scan (16 clusters x 8 CTAs, 4 batches/cluster).
//   EXACT R3 matvec structure (empirically fastest: 4-batch interleaved,
//   4 accumulator chains). No per-thread DSMEM address cache (per-step mapa).
//   Broadcast + cluster barrier skipped on the final step.
// ---------------------------------------------------------------------------
#define CLUSTER_C 8
#define NCLUST 16
#define BPC 4
#define DLOC 64
#define SCAN_THREADS 512
#define BEL_BUF_BYTES (BPC*DD*4)   // 8192

__global__ __launch_bounds__(SCAN_THREADS, 1) __cluster_dims__(CLUSTER_C, 1, 1)
void scan_cluster_kernel(const float* __restrict__ Wp, const float* __restrict__ bp,
                         float* __restrict__ out)
{
    __shared__ __align__(16) float bel[2][BPC][DD];      // 16 KB double-buffered
    __shared__ __align__(16) float sp[BPC][8][DLOC];     // 8 KB partials

    const int tid     = threadIdx.x;
    const int d_local = tid & 63;
    const int ksec    = tid >> 6;        // 0..7
    const int kbase   = ksec * 64;

    uint32_t rank;
    asm("mov.u32 %0, %%cluster_ctarank;" : "=r"(rank));
    const int cluster_id = blockIdx.x / CLUSTER_C;
    const int b0    = cluster_id * BPC;
    const int dglob = (int)rank * DLOC + d_local;

    // ---- Persistent Wp slice in registers ----
    float w[64];
    #pragma unroll
    for (int j = 0; j < 64; j++)
        w[j] = Wp[(size_t)(kbase + j) * DD + dglob];

    // ---- init belief buffer 0 ----
    for (int i = tid; i < BPC * DD; i += SCAN_THREADS)
        (&bel[0][0][0])[i] = 0.0f;

    // ---- reducer state ----
    const int  rb     = ksec & 3;
    const bool is_red = (tid < 256);
    float bel_prev = 0.0f;
    float bpv = 0.0f;
    size_t io_base = 0;
    uint32_t la_base = 0;
    if (is_red) {
        bpv = bp[dglob];
        io_base = ((size_t)(b0 + rb) * TT) * DD + dglob;
        la_base = (uint32_t)__cvta_generic_to_shared(&bel[0][rb][dglob]);
    }

    asm volatile("barrier.cluster.arrive.aligned;" ::: "memory");
    asm volatile("barrier.cluster.wait.aligned;"   ::: "memory");

    for (int t = 0; t < TT; t++) {
        const int cur = t & 1;

        // prefetch gate inputs (latency hidden under matvec)
        float evv = 0.f, lkv = 0.f, wrv = 0.f;
        if (is_red) {
            const size_t idx = io_base + (size_t)t * DD;
            evv = g_ev[idx];
            lkv = g_leak[idx];
            wrv = g_write[idx];
        }

        // ---- matvec partials: R3 structure (4-batch interleave) ----
        const float4* bl0 = (const float4*)&bel[cur][0][kbase];
        const float4* bl1 = (const float4*)&bel[cur][1][kbase];
        const float4* bl2 = (const float4*)&bel[cur][2][kbase];
        const float4* bl3 = (const float4*)&bel[cur][3][kbase];
        float a0 = 0.f, a1 = 0.f, a2 = 0.f, a3 = 0.f;
        #pragma unroll
        for (int j4 = 0; j4 < 16; j4++) {
            const float4 v0 = bl0[j4];
            const float4 v1 = bl1[j4];
            const float4 v2 = bl2[j4];
            const float4 v3 = bl3[j4];
            a0 = fmaf(v0.x, w[4*j4+0], a0);
            a0 = fmaf(v0.y, w[4*j4+1], a0);
            a0 = fmaf(v0.z, w[4*j4+2], a0);
            a0 = fmaf(v0.w, w[4*j4+3], a0);
            a1 = fmaf(v1.x, w[4*j4+0], a1);
            a1 = fmaf(v1.y, w[4*j4+1], a1);
            a1 = fmaf(v1.z, w[4*j4+2], a1);
            a1 = fmaf(v1.w, w[4*j4+3], a1);
            a2 = fmaf(v2.x, w[4*j4+0], a2);
            a2 = fmaf(v2.y, w[4*j4+1], a2);
            a2 = fmaf(v2.z, w[4*j4+2], a2);
            a2 = fmaf(v2.w, w[4*j4+3], a2);
            a3 = fmaf(v3.x, w[4*j4+0], a3);
            a3 = fmaf(v3.y, w[4*j4+1], a3);
            a3 = fmaf(v3.z, w[4*j4+2], a3);
            a3 = fmaf(v3.w, w[4*j4+3], a3);
        }
        sp[0][ksec][d_local] = a0;
        sp[1][ksec][d_local] = a1;
        sp[2][ksec][d_local] = a2;
        sp[3][ksec][d_local] = a3;
        __syncthreads();

        // ---- reduce + gates + DSMEM broadcast ----
        const bool last = (t == TT - 1);
        if (is_red) {
            float s = 0.f;
            #pragma unroll
            for (int q = 0; q < 8; q++) s += sp[rb][q][d_local];
            const float cand = tanhf(s + bpv + evv);
            const float nb   = lkv * bel_prev + wrv * cand;
            bel_prev = nb;

            if (!last) {
                const uint32_t la = la_base + (cur ? 0u : (uint32_t)BEL_BUF_BYTES);
                #pragma unroll
                for (int p = 0; p < CLUSTER_C; p++) {
                    uint32_t ra;
                    asm("mapa.shared::cluster.u32 %0, %1, %2;"
                        : "=r"(ra) : "r"(la), "r"(p));
                    asm volatile("st.shared::cluster.f32 [%0], %1;"
                                 :: "r"(ra), "f"(nb) : "memory");
                }
            }
            out[io_base + (size_t)t * DD] = nb;
        }

        if (!last) {
            // orders DSMEM writes(t) before reads(t+1); protects sp reuse.
            asm volatile("barrier.cluster.arrive.aligned;" ::: "memory");
            asm volatile("barrier.cluster.wait.aligned;"   ::: "memory");
        }
    }
}

// ---------------------------------------------------------------------------
// Launch
// ---------------------------------------------------------------------------
extern "C" void kernel_launch(void* const* d_in, const int* in_sizes, int n_in,
                              void* d_out, int out_size)
{
    const float* evseq = (const float*)d_in[0];
    const float* We    = (const float*)d_in[1];
    const float* be    = (const float*)d_in[2];
    const float* Wp    = (const float*)d_in[3];
    const float* bp    = (const float*)d_in[4];
    const float* Wl    = (const float*)d_in[5];
    const float* bl    = (const float*)d_in[6];
    const float* Ww    = (const float*)d_in[7];
    const float* bw    = (const float*)d_in[8];
    float* out = (float*)d_out;

    float *p_ev, *p_leak, *p_write;
    cudaGetSymbolAddress((void**)&p_ev,    g_ev);
    cudaGetSymbolAddress((void**)&p_leak,  g_leak);
    cudaGetSymbolAddress((void**)&p_write, g_write);

    dim3 grid(MM / 128, DD / 128);
    dim3 blk(256);
    proj_gemm<0><<<grid, blk>>>(evseq, We, be, p_ev);
    proj_gemm<1><<<grid, blk>>>(evseq, Wl, bl, p_leak);
    proj_gemm<1><<<grid, blk>>>(evseq, Ww, bw, p_write);

    scan_cluster_kernel<<<NCLUST * CLUSTER_C, SCAN_THREADS>>>(Wp, bp, out);
}

// round 9
// speedup vs baseline: 1.8161x; 1.1560x over previous
#include <cuda_runtime.h>
#include <math.h>
#include <stdint.h>

#define BB 64
#define TT 512
#define DD 512
#define MM (BB*TT)   // 32768

typedef unsigned long long u64;

// Scratch for the precomputed projections (192 MB total)
__device__ float g_ev[MM*DD];
__device__ float g_leak[MM*DD];
__device__ float g_write[MM*DD];

// ---- packed fp32x2 helpers (Blackwell f32x2 pipe; exact IEEE fp32) ----
__device__ __forceinline__ u64 pack2(float lo, float hi) {
    u64 r; asm("mov.b64 %0, {%1, %2};" : "=l"(r) : "f"(lo), "f"(hi)); return r;
}
__device__ __forceinline__ void unpack2(u64 v, float& lo, float& hi) {
    asm("mov.b64 {%0, %1}, %2;" : "=f"(lo), "=f"(hi) : "l"(v));
}
__device__ __forceinline__ u64 ffma2(u64 a, u64 b, u64 c) {
    u64 d; asm("fma.rn.f32x2 %0, %1, %2, %3;" : "=l"(d) : "l"(a), "l"(b), "l"(c));
    return d;
}

// ---------------------------------------------------------------------------
// Kernel A: Y[m][n] = act( sum_k X[m][k]*W[k][n] + bias[n] )
// BM=128, BN=128, BK=16, 256 threads, 8x8 tile, f32x2 inner loop.
// As stored k-major so per-kk 'a' loads are 2x LDS.128 instead of 8 scalar.
// ---------------------------------------------------------------------------
template<int ACT>
__global__ __launch_bounds__(256, 2)
void proj_gemm(const float* __restrict__ X, const float* __restrict__ W,
               const float* __restrict__ bias, float* __restrict__ Y)
{
    constexpr int BM = 128, BN = 128, BK = 16;
    __shared__ __align__(16) float As[BK*BM];   // [k][m]  (m contiguous)
    __shared__ __align__(16) float Bs[BK*BN];   // [k][n]  (n contiguous)

    const int tid = threadIdx.x;
    const int m0 = blockIdx.x * BM;
    const int n0 = blockIdx.y * BN;
    const int tx = tid & 15;
    const int ty = tid >> 4;

    const int arow = tid >> 2;          // 0..63 (rows arow, arow+64)
    const int acol = (tid & 3) * 4;     // k offset 0,4,8,12
    const int brow = tid >> 5;
    const int bcol = (tid & 31) * 4;

    u64 acc2[8][4];
    #pragma unroll
    for (int i = 0; i < 8; i++)
        #pragma unroll
        for (int j = 0; j < 4; j++) acc2[i][j] = 0ULL;

    for (int k0 = 0; k0 < DD; k0 += BK) {
        float4 a0 = *(const float4*)&X[(size_t)(m0 + arow     ) * DD + k0 + acol];
        float4 a1 = *(const float4*)&X[(size_t)(m0 + arow + 64) * DD + k0 + acol];
        float4 b0 = *(const float4*)&W[(size_t)(k0 + brow    ) * DD + n0 + bcol];
        float4 b1 = *(const float4*)&W[(size_t)(k0 + brow + 8) * DD + n0 + bcol];
        // transpose-store A: As[k][m]
        As[(acol + 0) * BM + arow] = a0.x;
        As[(acol + 1) * BM + arow] = a0.y;
        As[(acol + 2) * BM + arow] = a0.z;
        As[(acol + 3) * BM + arow] = a0.w;
        As[(acol + 0) * BM + arow + 64] = a1.x;
        As[(acol + 1) * BM + arow + 64] = a1.y;
        As[(acol + 2) * BM + arow + 64] = a1.z;
        As[(acol + 3) * BM + arow + 64] = a1.w;
        *(float4*)&Bs[(brow    ) * BN + bcol] = b0;
        *(float4*)&Bs[(brow + 8) * BN + bcol] = b1;
        __syncthreads();

        #pragma unroll
        for (int kk = 0; kk < BK; kk++) {
            float4 aA = *(const float4*)&As[kk * BM + ty * 8];
            float4 aB = *(const float4*)&As[kk * BM + ty * 8 + 4];
            ulonglong2 bp0 = *(const ulonglong2*)&Bs[kk * BN + tx * 8];
            ulonglong2 bp1 = *(const ulonglong2*)&Bs[kk * BN + tx * 8 + 4];
            u64 b2[4] = { bp0.x, bp0.y, bp1.x, bp1.y };
            float av[8] = { aA.x, aA.y, aA.z, aA.w, aB.x, aB.y, aB.z, aB.w };
            #pragma unroll
            for (int i = 0; i < 8; i++) {
                const u64 ap = pack2(av[i], av[i]);
                #pragma unroll
                for (int j = 0; j < 4; j++)
                    acc2[i][j] = ffma2(ap, b2[j], acc2[i][j]);
            }
        }
        __syncthreads();
    }

    #pragma unroll
    for (int i = 0; i < 8; i++) {
        const int m = m0 + ty * 8 + i;
        #pragma unroll
        for (int j = 0; j < 4; j++) {
            float lo, hi;
            unpack2(acc2[i][j], lo, hi);
            const int n = n0 + tx * 8 + 2 * j;
            float v0 = lo + bias[n];
            float v1 = hi + bias[n + 1];
            if (ACT == 1) {
                v0 = 1.0f / (1.0f + expf(-v0));
                v1 = 1.0f / (1.0f + expf(-v1));
            }
            Y[(size_t)m * DD + n]     = v0;
            Y[(size_t)m * DD + n + 1] = v1;
        }
    }
}

// ---------------------------------------------------------------------------
// Kernel B: cluster-resident scan with mbarrier-tx pipeline (no cluster
// barrier in the loop, no scalar remote stores).
//   16 clusters x 8 CTAs, 4 batches/cluster. Wp slice in registers.
//   Belief layout bel[2][rank][batch][64]: each CTA's slice is 1KB
//   contiguous; broadcast = 8x cp.async.bulk (1KB) w/ complete_tx on the
//   destination's full-mbarrier (expect_tx = 8KB per phase).
// ---------------------------------------------------------------------------
#define CLUSTER_C 8
#define NCLUST 16
#define BPC 4
#define DLOC 64
#define SCAN_THREADS 512
#define SLICE_BYTES (BPC*DLOC*4)     // 1024
#define STEP_BYTES  (CLUSTER_C*SLICE_BYTES)  // 8192

__global__ __launch_bounds__(SCAN_THREADS, 1) __cluster_dims__(CLUSTER_C, 1, 1)
void scan_cluster_kernel(const float* __restrict__ Wp, const float* __restrict__ bp,
                         float* __restrict__ out)
{
    __shared__ __align__(16) float bel[2][CLUSTER_C][BPC][DLOC];  // 16 KB
    __shared__ __align__(16) float sp[BPC][8][DLOC];              // 8 KB
    __shared__ __align__(16) float stage[2][BPC][DLOC];           // 2 KB
    __shared__ __align__(8)  u64  full_mbar[2];

    const int tid     = threadIdx.x;
    const int d_local = tid & 63;
    const int ksec    = tid >> 6;        // 0..7
    const int kbase   = ksec * 64;

    uint32_t rank;
    asm("mov.u32 %0, %%cluster_ctarank;" : "=r"(rank));
    const int cluster_id = blockIdx.x / CLUSTER_C;
    const int b0    = cluster_id * BPC;
    const int dglob = (int)rank * DLOC + d_local;

    // ---- Persistent Wp slice in registers ----
    float w[64];
    #pragma unroll
    for (int j = 0; j < 64; j++)
        w[j] = Wp[(size_t)(kbase + j) * DD + dglob];

    // ---- init belief buffer 0 + mbarriers ----
    for (int i = tid; i < CLUSTER_C * BPC * DLOC; i += SCAN_THREADS)
        (&bel[0][0][0][0])[i] = 0.0f;
    const uint32_t mb0 = (uint32_t)__cvta_generic_to_shared(&full_mbar[0]);
    const uint32_t mb1 = (uint32_t)__cvta_generic_to_shared(&full_mbar[1]);
    if (tid == 0) {
        asm volatile("mbarrier.init.shared.b64 [%0], 1;" :: "r"(mb0) : "memory");
        asm volatile("mbarrier.init.shared.b64 [%0], 1;" :: "r"(mb1) : "memory");
    }
    __syncthreads();

    // ---- reducer state: threads 0..255, one per (batch, column) ----
    const int  rb     = ksec & 3;
    const bool is_red = (tid < 256);
    float bel_prev = 0.0f;
    float bpv = 0.0f;
    size_t io_base = 0;
    if (is_red) {
        bpv = bp[dglob];
        io_base = ((size_t)(b0 + rb) * TT) * DD + dglob;
    }

    // one cluster sync: all CTAs' bel[0] + mbarriers ready before any traffic
    asm volatile("barrier.cluster.arrive.aligned;" ::: "memory");
    asm volatile("barrier.cluster.wait.aligned;"   ::: "memory");

    int ph0 = 0, ph1 = 0;

    for (int t = 0; t < TT; t++) {
        const int cur = t & 1;
        const int nxt = cur ^ 1;

        // gate prefetch BEFORE the wait: DRAM latency hides under wait+matvec
        float evv = 0.f, lkv = 0.f, wrv = 0.f;
        if (is_red) {
            const size_t idx = io_base + (size_t)t * DD;
            evv = g_ev[idx];
            lkv = g_leak[idx];
            wrv = g_write[idx];
        }

        // ---- wait for bel[cur] (written during step t-1) ----
        if (t > 0) {
            const uint32_t mb = cur ? mb1 : mb0;
            const int ph = cur ? ph1 : ph0;
            uint32_t done;
            asm volatile(
                "{\n\t.reg .pred p;\n\t"
                "mbarrier.try_wait.parity.acquire.cta.shared::cta.b64 p, [%1], %2;\n\t"
                "selp.b32 %0, 1, 0, p;\n\t}"
                : "=r"(done) : "r"(mb), "r"(ph) : "memory");
            if (!done) {
                asm volatile(
                    "{\n\t.reg .pred P1;\n\t"
                    "W%=:\n\t"
                    "mbarrier.try_wait.parity.acquire.cta.shared::cta.b64 P1, [%0], %1, 0x989680;\n\t"
                    "@P1 bra.uni D%=;\n\t"
                    "bra.uni W%=;\n\t"
                    "D%=:\n\t}"
                    :: "r"(mb), "r"(ph) : "memory");
            }
            if (cur) ph1 ^= 1; else ph0 ^= 1;
        }

        // ---- matvec partials: 4-batch interleave (R3-proven structure) ----
        const float4* bl0 = (const float4*)&bel[cur][ksec][0][0];
        const float4* bl1 = (const float4*)&bel[cur][ksec][1][0];
        const float4* bl2 = (const float4*)&bel[cur][ksec][2][0];
        const float4* bl3 = (const float4*)&bel[cur][ksec][3][0];
        float a0 = 0.f, a1 = 0.f, a2 = 0.f, a3 = 0.f;
        #pragma unroll
        for (int j4 = 0; j4 < 16; j4++) {
            const float4 v0 = bl0[j4];
            const float4 v1 = bl1[j4];
            const float4 v2 = bl2[j4];
            const float4 v3 = bl3[j4];
            a0 = fmaf(v0.x, w[4*j4+0], a0);
            a0 = fmaf(v0.y, w[4*j4+1], a0);
            a0 = fmaf(v0.z, w[4*j4+2], a0);
            a0 = fmaf(v0.w, w[4*j4+3], a0);
            a1 = fmaf(v1.x, w[4*j4+0], a1);
            a1 = fmaf(v1.y, w[4*j4+1], a1);
            a1 = fmaf(v1.z, w[4*j4+2], a1);
            a1 = fmaf(v1.w, w[4*j4+3], a1);
            a2 = fmaf(v2.x, w[4*j4+0], a2);
            a2 = fmaf(v2.y, w[4*j4+1], a2);
            a2 = fmaf(v2.z, w[4*j4+2], a2);
            a2 = fmaf(v2.w, w[4*j4+3], a2);
            a3 = fmaf(v3.x, w[4*j4+0], a3);
            a3 = fmaf(v3.y, w[4*j4+1], a3);
            a3 = fmaf(v3.z, w[4*j4+2], a3);
            a3 = fmaf(v3.w, w[4*j4+3], a3);
        }
        sp[0][ksec][d_local] = a0;
        sp[1][ksec][d_local] = a1;
        sp[2][ksec][d_local] = a2;
        sp[3][ksec][d_local] = a3;
        __syncthreads();

        // ---- reduce + gates -> staging ----
        if (is_red) {
            float s = 0.f;
            #pragma unroll
            for (int q = 0; q < 8; q++) s += sp[rb][q][d_local];
            const float cand = tanhf(s + bpv + evv);
            const float nb   = lkv * bel_prev + wrv * cand;
            bel_prev = nb;
            stage[cur][rb][d_local] = nb;
            out[io_base + (size_t)t * DD] = nb;
        }
        __syncthreads();   // staging complete before async source reads

        // ---- broadcast: 8x 1KB bulk copies w/ complete_tx on dest barrier ----
        if (t < TT - 1 && tid == 0) {
            asm volatile("fence.proxy.async.shared::cta;" ::: "memory");
            const uint32_t mb_l = nxt ? mb1 : mb0;
            // arm my own barrier for the incoming 8KB of this phase
            asm volatile(
                "mbarrier.arrive.expect_tx.shared.b64 _, [%0], %1;"
                :: "r"(mb_l), "r"((uint32_t)STEP_BYTES) : "memory");
            const uint32_t src = (uint32_t)__cvta_generic_to_shared(&stage[cur][0][0]);
            const uint32_t dst_l =
                (uint32_t)__cvta_generic_to_shared(&bel[nxt][rank][0][0]);
            #pragma unroll
            for (int p = 0; p < CLUSTER_C; p++) {
                uint32_t dst_r, mb_r;
                asm("mapa.shared::cluster.u32 %0, %1, %2;"
                    : "=r"(dst_r) : "r"(dst_l), "r"(p));
                asm("mapa.shared::cluster.u32 %0, %1, %2;"
                    : "=r"(mb_r) : "r"(mb_l), "r"(p));
                asm volatile(
                    "cp.async.bulk.shared::cluster.shared::cta.mbarrier::complete_tx::bytes "
                    "[%0], [%1], %2, [%3];"
                    :: "r"(dst_r), "r"(src), "r"((uint32_t)SLICE_BYTES), "r"(mb_r)
                    : "memory");
            }
        }
    }
}

// ---------------------------------------------------------------------------
// Launch
// ---------------------------------------------------------------------------
extern "C" void kernel_launch(void* const* d_in, const int* in_sizes, int n_in,
                              void* d_out, int out_size)
{
    const float* evseq = (const float*)d_in[0];
    const float* We    = (const float*)d_in[1];
    const float* be    = (const float*)d_in[2];
    const float* Wp    = (const float*)d_in[3];
    const float* bp    = (const float*)d_in[4];
    const float* Wl    = (const float*)d_in[5];
    const float* bl    = (const float*)d_in[6];
    const float* Ww    = (const float*)d_in[7];
    const float* bw    = (const float*)d_in[8];
    float* out = (float*)d_out;

    float *p_ev, *p_leak, *p_write;
    cudaGetSymbolAddress((void**)&p_ev,    g_ev);
    cudaGetSymbolAddress((void**)&p_leak,  g_leak);
    cudaGetSymbolAddress((void**)&p_write, g_write);

    dim3 grid(MM / 128, DD / 128);
    dim3 blk(256);
    proj_gemm<0><<<grid, blk>>>(evseq, We, be, p_ev);
    proj_gemm<1><<<grid, blk>>>(evseq, Wl, bl, p_leak);
    proj_gemm<1><<<grid, blk>>>(evseq, Ww, bw, p_write);

    scan_cluster_kernel<<<NCLUST * CLUSTER_C, SCAN_THREADS>>>(Wp, bp, out);
}